// round 6
// baseline (speedup 1.0000x reference)
#include <cuda_runtime.h>
#include <math.h>

// Problem dims (fixed by the dataset)
#define Bn 32
#define Tn 256
#define Nn 1024
#define Mn 1024
#define G4 4096           // 4*M gate rows per layer
#define KB 64             // K-chunk per SMEM stage
#define NCHUNK 32         // 2048 / KB  (seg0: input K=1024, seg1: recurrent K=1024)
#define UNITS_PER_CTA 16
#define TILES_PER_LAYER 64  // 1024 / 16

// Padded SMEM strides (float counts). Both keep 16B/8B vector alignment.
#define WSTRIDE 72
#define ASTRIDE 34

// ---------------- persistent device state (scratch; no allocs) ----------------
__device__ float g_h0[2][Bn * Mn];   // layer0 h, double buffered
__device__ float g_h1[2][Bn * Mn];   // layer1 h, double buffered
__device__ float g_c0[Bn * Mn];      // layer0 c
__device__ float g_c1[Bn * Mn];      // layer1 c

__device__ __forceinline__ float sigmoidf_(float z) {
    return 1.0f / (1.0f + expf(-z));
}

// ---------------- init: copy initial h, c into scratch ----------------
__global__ void lstm_init_kernel(const float* __restrict__ h,
                                 const float* __restrict__ c) {
    int i = blockIdx.x * blockDim.x + threadIdx.x;
    if (i < Bn * Mn) {
        g_h0[0][i] = h[i];
        g_c0[i]    = c[i];
    } else if (i < 2 * Bn * Mn) {
        int j = i - Bn * Mn;
        g_h1[0][j] = h[i];
        g_c1[j]    = c[i];
    }
}

// ---------------- final: pack h_final, c_final into d_out tail ----------------
// After step T-1 (odd T-1=255), both layers' final h live in buffer 0.
__global__ void lstm_final_kernel(float* __restrict__ out) {
    int i = blockIdx.x * blockDim.x + threadIdx.x;
    if (i >= 2 * Bn * Mn) return;
    const int base = Bn * Tn * Mn;           // outs size
    float hv, cv;
    if (i < Bn * Mn) { hv = g_h0[0][i];            cv = g_c0[i]; }
    else             { hv = g_h1[0][i - Bn * Mn];  cv = g_c1[i - Bn * Mn]; }
    out[base + i] = hv;                       // h_final (L,B,M)
    out[base + 2 * Bn * Mn + i] = cv;         // c_final (L,B,M)
}

// ---------------- skewed step kernel ----------------
// Launch t in [0..T]: blocks 0..63  -> layer 0, step t      (active for t <  T)
//                     blocks 64..127-> layer 1, step t - 1  (active for t >= 1)
// Each CTA: 16 hidden units (64 gate rows) x 32 batch, K = 1024(input)+1024(recurrent).
// Thread (ulocal = tid>>4, bpair = tid&15) accumulates the 4 gates of ONE unit
// for 2 batches -> fully local LSTM pointwise epilogue.
__global__ __launch_bounds__(256, 1)
void lstm_step_kernel(int t,
                      const float* __restrict__ x,
                      const float* __restrict__ Wih,
                      const float* __restrict__ Whh,
                      const float* __restrict__ bih,
                      const float* __restrict__ bhh,
                      float* __restrict__ out) {
    const int layer = blockIdx.x >> 6;
    const int tile  = blockIdx.x & 63;
    if (layer == 0 && t >= Tn) return;
    if (layer == 1 && t == 0)  return;
    const int s = (layer == 0) ? t : (t - 1);   // the step this CTA computes

    const int U      = tile * UNITS_PER_CTA;    // first hidden unit of this CTA
    const int tid    = threadIdx.x;
    const int ulocal = tid >> 4;                // 0..15 unit within tile
    const int bpair  = tid & 15;                // 0..15 batch pair

    const float* W0 = Wih + (size_t)layer * G4 * Nn;   // input-projection weights
    const float* W1 = Whh + (size_t)layer * G4 * Mn;   // recurrent weights

    const float* A0; size_t a0s;   // seg0 input activations [b][k], batch stride a0s
    const float* A1;               // seg1 recurrent h       [b][k], stride Mn
    float* hout; float* cst;
    if (layer == 0) {
        A0   = x + (size_t)t * Nn;  a0s = (size_t)Tn * Nn;   // x[b][t][k]
        A1   = g_h0[t & 1];                                   // h0^(t-1)
        hout = g_h0[(t & 1) ^ 1];                             // h0^(t)
        cst  = g_c0;
    } else {
        A0   = g_h0[t & 1];         a0s = (size_t)Mn;         // h0^(s) = h0^(t-1)
        A1   = g_h1[s & 1];                                   // h1^(s-1)
        hout = g_h1[(s & 1) ^ 1];                             // h1^(s)
        cst  = g_c1;
    }

    __shared__ __align__(16) float smW[KB * WSTRIDE];  // [kk][row], row = ulocal*4+gate
    __shared__ __align__(16) float smA[KB * ASTRIDE];  // [kk][batch]

    float acc[4][2];
#pragma unroll
    for (int g = 0; g < 4; g++) { acc[g][0] = 0.0f; acc[g][1] = 0.0f; }

    // --- per-thread loader constants ---
    // W: 4 float4 per chunk. f4id = tid + i*256 -> srow = f4id>>4 (0..63), kq = f4id&15.
    int wsrow[4], wk4[4];
    size_t woff[4];
#pragma unroll
    for (int i = 0; i < 4; i++) {
        int f4   = tid + (i << 8);
        int srow = f4 >> 4;
        int kq   = f4 & 15;
        int u    = srow >> 2;
        int g    = srow & 3;
        wsrow[i] = srow;
        wk4[i]   = kq << 2;
        woff[i]  = (size_t)((g << 10) + U + u) * 1024 + (kq << 2);  // row*K + kq*4
    }
    // A: 2 float4 per chunk. b = f4id>>4 (0..31), kq = f4id&15.
    int ab[2], ak4[2];
#pragma unroll
    for (int i = 0; i < 2; i++) {
        int f4 = tid + (i << 8);
        ab[i]  = f4 >> 4;
        ak4[i] = (f4 & 15) << 2;
    }

    float4 rw[4], ra[2];

#define FETCH(c)                                                              \
    do {                                                                      \
        int   seg_ = (c) >> 4;                                                \
        int   k0_  = ((c) & 15) * KB;                                         \
        const float* Wseg_ = seg_ ? W1 : W0;                                  \
        const float* Aseg_ = seg_ ? A1 : A0;                                  \
        size_t as_ = seg_ ? (size_t)Mn : a0s;                                 \
        _Pragma("unroll")                                                     \
        for (int i_ = 0; i_ < 4; i_++)                                        \
            rw[i_] = *reinterpret_cast<const float4*>(Wseg_ + woff[i_] + k0_);\
        _Pragma("unroll")                                                     \
        for (int i_ = 0; i_ < 2; i_++)                                        \
            ra[i_] = *reinterpret_cast<const float4*>(                        \
                Aseg_ + (size_t)ab[i_] * as_ + k0_ + ak4[i_]);                \
    } while (0)

    FETCH(0);

    for (int c = 0; c < NCHUNK; c++) {
        __syncthreads();   // previous chunk's compute done before overwrite
        // stage W: float4 spans 4 consecutive kk at one row
#pragma unroll
        for (int i = 0; i < 4; i++) {
            int kk = wk4[i], srow = wsrow[i];
            smW[(kk + 0) * WSTRIDE + srow] = rw[i].x;
            smW[(kk + 1) * WSTRIDE + srow] = rw[i].y;
            smW[(kk + 2) * WSTRIDE + srow] = rw[i].z;
            smW[(kk + 3) * WSTRIDE + srow] = rw[i].w;
        }
#pragma unroll
        for (int i = 0; i < 2; i++) {
            int kk = ak4[i], b = ab[i];
            smA[(kk + 0) * ASTRIDE + b] = ra[i].x;
            smA[(kk + 1) * ASTRIDE + b] = ra[i].y;
            smA[(kk + 2) * ASTRIDE + b] = ra[i].z;
            smA[(kk + 3) * ASTRIDE + b] = ra[i].w;
        }
        __syncthreads();

        if (c + 1 < NCHUNK) FETCH(c + 1);   // overlap next LDG with compute

#pragma unroll 16
        for (int kk = 0; kk < KB; kk++) {
            float4 w = *reinterpret_cast<const float4*>(
                &smW[kk * WSTRIDE + (ulocal << 2)]);
            float2 a = *reinterpret_cast<const float2*>(
                &smA[kk * ASTRIDE + (bpair << 1)]);
            acc[0][0] = fmaf(w.x, a.x, acc[0][0]);
            acc[0][1] = fmaf(w.x, a.y, acc[0][1]);
            acc[1][0] = fmaf(w.y, a.x, acc[1][0]);
            acc[1][1] = fmaf(w.y, a.y, acc[1][1]);
            acc[2][0] = fmaf(w.z, a.x, acc[2][0]);
            acc[2][1] = fmaf(w.z, a.y, acc[2][1]);
            acc[3][0] = fmaf(w.w, a.x, acc[3][0]);
            acc[3][1] = fmaf(w.w, a.y, acc[3][1]);
        }
    }
#undef FETCH

    // ---------------- epilogue: bias + LSTM cell update (register-local) ----------------
    const int m = U + ulocal;                 // hidden unit index
    const float* bi = bih + layer * G4;
    const float* bh = bhh + layer * G4;
    float z[4][2];
#pragma unroll
    for (int g = 0; g < 4; g++) {
        int j = (g << 10) + m;
        float bb = bi[j] + bh[j];
        z[g][0] = acc[g][0] + bb;
        z[g][1] = acc[g][1] + bb;
    }
#pragma unroll
    for (int p = 0; p < 2; p++) {
        int b   = (bpair << 1) + p;
        int idx = b * Mn + m;
        float ig = sigmoidf_(z[0][p]);
        float fg = sigmoidf_(z[1][p]);
        float gg = tanhf(z[2][p]);
        float og = sigmoidf_(z[3][p]);
        float cn = fmaf(fg, cst[idx], ig * gg);
        cst[idx] = cn;
        float hh = og * tanhf(cn);
        hout[idx] = hh;
        if (layer == 1)
            out[((size_t)b * Tn + s) * Mn + m] = hh;   // top-layer h -> outs[b][s][:]
    }
}

// ---------------- launch ----------------
extern "C" void kernel_launch(void* const* d_in, const int* in_sizes, int n_in,
                              void* d_out, int out_size) {
    (void)in_sizes; (void)n_in; (void)out_size;
    const float* x   = (const float*)d_in[0];
    const float* h   = (const float*)d_in[1];
    const float* c   = (const float*)d_in[2];
    const float* Wih = (const float*)d_in[3];
    const float* Whh = (const float*)d_in[4];
    const float* bih = (const float*)d_in[5];
    const float* bhh = (const float*)d_in[6];
    float* out = (float*)d_out;

    lstm_init_kernel<<<(2 * Bn * Mn + 255) / 256, 256>>>(h, c);

    // Skewed pipeline: launch t runs layer0 step t and layer1 step t-1.
    for (int t = 0; t <= Tn; ++t)
        lstm_step_kernel<<<2 * TILES_PER_LAYER, 256>>>(t, x, Wih, Whh, bih, bhh, out);

    lstm_final_kernel<<<(2 * Bn * Mn + 255) / 256, 256>>>(out);
}

// round 10
// speedup vs baseline: 3.6792x; 3.6792x over previous
#include <cuda_runtime.h>
#include <cuda_bf16.h>
#include <math.h>
#include <stdint.h>

// ---------------- problem dims ----------------
#define Bn 32
#define Tn 256
#define Nn 1024
#define Mn 1024
#define G4 4096
#define BM (Bn * Mn)
#define KC 64                 // K elems per chunk
#define NCHUNK 32             // 2048 / 64 (seg0 = input, seg1 = recurrent)
#define TILES 64              // CTAs per layer; 16 hidden units (64 gate rows) each
#define W_CHUNK_BYTES 16384   // 64 rows x 64 bf16 x (hi+lo) = 8KB + 8KB
#define STAGE_BYTES 24576     // W 16KB + A (4KB hi + 4KB lo)
#define A_HI_OFF 16384
#define A_LO_OFF 20480
#define SWZ(o) ((o) ^ (((o) >> 3) & 0x70))

// ---------------- persistent device state (static; no allocs) ----------------
__device__ float g_h0[2][BM];
__device__ float g_h1[2][BM];
__device__ float g_c0[BM];
__device__ float g_c1[BM];
__device__ __nv_bfloat16 g_h0bf[2][2][BM];          // [dbuf][hi/lo][b*1024+k]
__device__ __nv_bfloat16 g_h1bf[2][2][BM];
__device__ __nv_bfloat16 g_xbf[2][Bn * Tn * Nn];    // [hi/lo], same layout as x
__device__ unsigned char g_Wpk[(size_t)2 * TILES * NCHUNK * W_CHUNK_BYTES];  // 64MB

__device__ __forceinline__ float sigmoidf_(float z) { return 1.0f / (1.0f + expf(-z)); }

__device__ __forceinline__ uint32_t smem_u32(const void* p) {
    uint32_t a;
    asm("{ .reg .u64 t; cvta.to.shared.u64 t, %1; cvt.u32.u64 %0, t; }" : "=r"(a) : "l"(p));
    return a;
}

__device__ __forceinline__ void split2(float a, float b, uint32_t& hi, uint32_t& lo) {
    __nv_bfloat16 ha = __float2bfloat16(a), hb = __float2bfloat16(b);
    float ra = a - __bfloat162float(ha), rb = b - __bfloat162float(hb);
    __nv_bfloat16 la = __float2bfloat16(ra), lb = __float2bfloat16(rb);
    hi = (uint32_t)__bfloat16_as_ushort(ha) | ((uint32_t)__bfloat16_as_ushort(hb) << 16);
    lo = (uint32_t)__bfloat16_as_ushort(la) | ((uint32_t)__bfloat16_as_ushort(lb) << 16);
}

#define LDSM4(R, A)                                                                  \
    asm volatile("ldmatrix.sync.aligned.m8n8.x4.shared.b16 {%0,%1,%2,%3}, [%4];"     \
                 : "=r"((R)[0]), "=r"((R)[1]), "=r"((R)[2]), "=r"((R)[3]) : "r"(A))

#define MMA16816(D, Av, B0, B1)                                                      \
    asm volatile("mma.sync.aligned.m16n8k16.row.col.f32.bf16.bf16.f32 "              \
                 "{%0,%1,%2,%3},{%4,%5,%6,%7},{%8,%9},{%0,%1,%2,%3};"                \
                 : "+f"((D)[0]), "+f"((D)[1]), "+f"((D)[2]), "+f"((D)[3])            \
                 : "r"((Av)[0]), "r"((Av)[1]), "r"((Av)[2]), "r"((Av)[3]),           \
                   "r"(B0), "r"(B1))

#define CPA16(dst, src) \
    asm volatile("cp.async.ca.shared.global [%0], [%1], 16;" :: "r"(dst), "l"(src))

// ---------------- init ----------------
__global__ void lstm_init_kernel(const float* __restrict__ h, const float* __restrict__ c) {
    int i = blockIdx.x * blockDim.x + threadIdx.x;
    if (i < BM) {
        float hv = h[i];
        g_h0[0][i] = hv;  g_c0[i] = c[i];
        __nv_bfloat16 hi = __float2bfloat16(hv);
        g_h0bf[0][0][i] = hi;
        g_h0bf[0][1][i] = __float2bfloat16(hv - __bfloat162float(hi));
    } else if (i < 2 * BM) {
        int j = i - BM;
        float hv = h[i];
        g_h1[0][j] = hv;  g_c1[j] = c[i];
        __nv_bfloat16 hi = __float2bfloat16(hv);
        g_h1bf[0][0][j] = hi;
        g_h1bf[0][1][j] = __float2bfloat16(hv - __bfloat162float(hi));
    }
}

// ---------------- final ----------------
__global__ void lstm_final_kernel(float* __restrict__ out) {
    int i = blockIdx.x * blockDim.x + threadIdx.x;
    if (i >= 2 * BM) return;
    const int base = Bn * Tn * Mn;
    float hv, cv;
    if (i < BM) { hv = g_h0[0][i];      cv = g_c0[i]; }
    else        { hv = g_h1[0][i - BM]; cv = g_c1[i - BM]; }
    out[base + i] = hv;
    out[base + 2 * BM + i] = cv;
}

// ---------------- pack x: fp32 -> bf16 hi/lo ----------------
__global__ void pack_x_kernel(const float* __restrict__ x) {
    int idx = blockIdx.x * blockDim.x + threadIdx.x;   // one thread per 4 elems
    float4 v = *reinterpret_cast<const float4*>(x + (size_t)idx * 4);
    uint32_t h0, l0, h1, l1;
    split2(v.x, v.y, h0, l0);
    split2(v.z, v.w, h1, l1);
    *reinterpret_cast<uint2*>((char*)g_xbf[0] + (size_t)idx * 8) = make_uint2(h0, h1);
    *reinterpret_cast<uint2*>((char*)g_xbf[1] + (size_t)idx * 8) = make_uint2(l0, l1);
}

// ---------------- pack weights: fp32 -> bf16 hi/lo, tile/chunk-major, pre-swizzled ----------------
// thread per 8-byte granule (4 k elems). Tile row r in [0,64): gate = r>>4, ul = r&15.
__global__ void pack_weights_kernel(const float* __restrict__ Wih, const float* __restrict__ Whh) {
    int idx = blockIdx.x * blockDim.x + threadIdx.x;   // 2*64*32*1024 = 4,194,304
    int k4    = idx & 15;
    int r     = (idx >> 4) & 63;
    int chunk = (idx >> 10) & 31;
    int tile  = (idx >> 15) & 63;
    int l     = (idx >> 21) & 1;
    int gate = r >> 4, ul = r & 15;
    int R = gate * 1024 + tile * 16 + ul;
    int seg = chunk >> 4, k0 = (chunk & 15) * KC;
    const float* W = seg ? Whh : Wih;
    float4 v = *reinterpret_cast<const float4*>(W + ((size_t)l * G4 + R) * 1024 + k0 + k4 * 4);
    uint32_t h0, l0, h1, l1;
    split2(v.x, v.y, h0, l0);
    split2(v.z, v.w, h1, l1);
    size_t base = (size_t)((l * TILES + tile) * NCHUNK + chunk) * W_CHUNK_BYTES;
    uint32_t sw = SWZ((uint32_t)(r * 128 + k4 * 8));
    *reinterpret_cast<uint2*>(g_Wpk + base + sw)        = make_uint2(h0, h1);  // hi (8KB)
    *reinterpret_cast<uint2*>(g_Wpk + base + 8192 + sw) = make_uint2(l0, l1);  // lo (8KB)
}

// ---------------- step kernel: skewed 2-layer, mma.sync bf16 3-term ----------------
// grid = 128: blocks 0..63 layer0 step t, 64..127 layer1 step t-1.
// CTA = 16 units (64 gate rows) x 32 batch. 8 warps:
//   rg = wid>>1 (16-row group), nh = wid&1 (16-batch half).
__global__ __launch_bounds__(256, 1)
void lstm_step_mma(int t,
                   const float* __restrict__ bih, const float* __restrict__ bhh,
                   float* __restrict__ out) {
    const int layer = blockIdx.x >> 6;
    const int tile  = blockIdx.x & 63;
    if (layer == 0 && t >= Tn) return;
    if (layer == 1 && t == 0)  return;
    const int s = layer ? (t - 1) : t;
    const int U = tile * 16;
    const int tid = threadIdx.x;
    const int wid = tid >> 5, lane = tid & 31;

    // activation sources (bf16 hi/lo, k-major rows) + state targets
    const char *hi0, *lo0, *hi1, *lo1;
    size_t st0;
    const size_t st1 = (size_t)Mn * 2;
    float* hout; float* cst;
    __nv_bfloat16 *hbo_hi, *hbo_lo;
    if (layer == 0) {
        hi0 = (const char*)g_xbf[0] + (size_t)t * Nn * 2;
        lo0 = (const char*)g_xbf[1] + (size_t)t * Nn * 2;
        st0 = (size_t)Tn * Nn * 2;
        hi1 = (const char*)g_h0bf[t & 1][0];
        lo1 = (const char*)g_h0bf[t & 1][1];
        hout = g_h0[(t & 1) ^ 1]; cst = g_c0;
        hbo_hi = g_h0bf[(t & 1) ^ 1][0]; hbo_lo = g_h0bf[(t & 1) ^ 1][1];
    } else {
        hi0 = (const char*)g_h0bf[t & 1][0];
        lo0 = (const char*)g_h0bf[t & 1][1];
        st0 = st1;
        hi1 = (const char*)g_h1bf[s & 1][0];
        lo1 = (const char*)g_h1bf[s & 1][1];
        hout = g_h1[(s & 1) ^ 1]; cst = g_c1;
        hbo_hi = g_h1bf[(s & 1) ^ 1][0]; hbo_lo = g_h1bf[(s & 1) ^ 1][1];
    }

    __shared__ __align__(128) char sm_[2 * STAGE_BYTES];   // 48KB, double buffered
    const uint32_t sb = smem_u32(sm_);
    const unsigned char* wsrc = g_Wpk + (size_t)((layer * TILES + tile) * NCHUNK) * W_CHUNK_BYTES;

    // per-warp / per-lane ldmatrix offsets (unswizzled; swizzle applied per step)
    const int rg = wid >> 1, nh = wid & 1;
    const uint32_t woff0 = (uint32_t)((rg * 16 + (lane & 15)) * 128 + (lane >> 4) * 16);
    const uint32_t aoff0 = (uint32_t)((nh * 16 + ((lane >> 4) << 3) + (lane & 7)) * 128
                                      + ((lane >> 3) & 1) * 16);

    float acc[6][4];
#pragma unroll
    for (int i = 0; i < 6; i++)
#pragma unroll
        for (int j = 0; j < 4; j++) acc[i][j] = 0.0f;

    // ---- fillers ----
#define FILL(buf_, chk_)                                                             \
    do {                                                                             \
        uint32_t d_ = sb + (buf_) * STAGE_BYTES;                                     \
        const unsigned char* ws_ = wsrc + (size_t)(chk_) * W_CHUNK_BYTES;            \
        _Pragma("unroll")                                                            \
        for (int i_ = 0; i_ < 4; i_++) {                                             \
            uint32_t o_ = i_ * 4096 + tid * 16;                                      \
            CPA16(d_ + o_, ws_ + o_);                                                \
        }                                                                            \
        int seg_ = (chk_) >> 4;                                                      \
        size_t kb_ = (size_t)((chk_) & 15) * KC * 2;                                 \
        const char* ah_ = seg_ ? hi1 : hi0;                                          \
        const char* al_ = seg_ ? lo1 : lo0;                                          \
        size_t as_ = seg_ ? st1 : st0;                                               \
        _Pragma("unroll")                                                            \
        for (int i_ = 0; i_ < 2; i_++) {                                             \
            int g_ = tid + (i_ << 8);                                                \
            int p_ = g_ >> 8, r_ = (g_ >> 3) & 31, kq_ = g_ & 7;                     \
            const char* s_ = (p_ ? al_ : ah_) + (size_t)r_ * as_ + kb_ + kq_ * 16;   \
            uint32_t dd_ = d_ + (p_ ? A_LO_OFF : A_HI_OFF) + SWZ((uint32_t)(r_ * 128 + kq_ * 16)); \
            CPA16(dd_, s_);                                                          \
        }                                                                            \
    } while (0)

    FILL(0, 0);
    asm volatile("cp.async.commit_group;" ::: "memory");

    for (int c = 0; c < NCHUNK; c++) {
        const int buf = c & 1;
        if (c + 1 < NCHUNK) {
            FILL(buf ^ 1, c + 1);
            asm volatile("cp.async.commit_group;" ::: "memory");
            asm volatile("cp.async.wait_group 1;" ::: "memory");
        } else {
            asm volatile("cp.async.wait_group 0;" ::: "memory");
        }
        __syncthreads();

        const uint32_t wb = sb + buf * STAGE_BYTES;
#pragma unroll
        for (int ks = 0; ks < 4; ks++) {
            uint32_t wo = woff0 + ks * 32;  wo = SWZ(wo);
            uint32_t ao = aoff0 + ks * 32;  ao = SWZ(ao);
            uint32_t whi[4], wlo[4], ahi[4], alo[4];
            LDSM4(whi, wb + wo);
            LDSM4(wlo, wb + 8192 + wo);
            LDSM4(ahi, wb + A_HI_OFF + ao);
            LDSM4(alo, wb + A_LO_OFF + ao);
            MMA16816(acc[0], whi, ahi[0], ahi[1]);   // ntile0: Whi.Ahi
            MMA16816(acc[3], whi, ahi[2], ahi[3]);   // ntile1: Whi.Ahi
            MMA16816(acc[1], wlo, ahi[0], ahi[1]);   // ntile0: Wlo.Ahi
            MMA16816(acc[4], wlo, ahi[2], ahi[3]);
            MMA16816(acc[2], whi, alo[0], alo[1]);   // ntile0: Whi.Alo
            MMA16816(acc[5], whi, alo[2], alo[3]);
        }
        __syncthreads();   // guard next FILL against this buffer's reads
    }
#undef FILL

    // ---- epilogue: accum frags -> smem z[64][33] -> register-local LSTM update ----
    float* z = (float*)sm_;
    {
        const int r0 = rg * 16 + (lane >> 2);
        const int c0 = nh * 16 + (lane & 3) * 2;
#pragma unroll
        for (int nt = 0; nt < 2; nt++) {
            float d0 = acc[nt * 3][0] + acc[nt * 3 + 1][0] + acc[nt * 3 + 2][0];
            float d1 = acc[nt * 3][1] + acc[nt * 3 + 1][1] + acc[nt * 3 + 2][1];
            float d2 = acc[nt * 3][2] + acc[nt * 3 + 1][2] + acc[nt * 3 + 2][2];
            float d3 = acc[nt * 3][3] + acc[nt * 3 + 1][3] + acc[nt * 3 + 2][3];
            int cc = c0 + nt * 8;
            z[r0 * 33 + cc]           = d0;
            z[r0 * 33 + cc + 1]       = d1;
            z[(r0 + 8) * 33 + cc]     = d2;
            z[(r0 + 8) * 33 + cc + 1] = d3;
        }
    }
    __syncthreads();

    // pointwise: thread -> unit ul, batches b2 and b2+16
    const int ul = tid & 15;
    const int b2 = tid >> 4;
    float bz[4];
#pragma unroll
    for (int g = 0; g < 4; g++) {
        int j = layer * G4 + g * 1024 + U + ul;
        bz[g] = bih[j] + bhh[j];
    }
#pragma unroll
    for (int i = 0; i < 2; i++) {
        int b = b2 + 16 * i;
        float zi = z[(0 * 16 + ul) * 33 + b] + bz[0];
        float zf = z[(1 * 16 + ul) * 33 + b] + bz[1];
        float zg = z[(2 * 16 + ul) * 33 + b] + bz[2];
        float zo = z[(3 * 16 + ul) * 33 + b] + bz[3];
        int idx = b * Mn + U + ul;
        float ig = sigmoidf_(zi), fg = sigmoidf_(zf), og = sigmoidf_(zo);
        float gg = tanhf(zg);
        float cn = fmaf(fg, cst[idx], ig * gg);
        cst[idx] = cn;
        float hh = og * tanhf(cn);
        hout[idx] = hh;
        __nv_bfloat16 hhi = __float2bfloat16(hh);
        hbo_hi[idx] = hhi;
        hbo_lo[idx] = __float2bfloat16(hh - __bfloat162float(hhi));
        if (layer == 1)
            out[((size_t)b * Tn + s) * Mn + U + ul] = hh;
    }
}

// ---------------- launch ----------------
extern "C" void kernel_launch(void* const* d_in, const int* in_sizes, int n_in,
                              void* d_out, int out_size) {
    (void)in_sizes; (void)n_in; (void)out_size;
    const float* x   = (const float*)d_in[0];
    const float* h   = (const float*)d_in[1];
    const float* c   = (const float*)d_in[2];
    const float* Wih = (const float*)d_in[3];
    const float* Whh = (const float*)d_in[4];
    const float* bih = (const float*)d_in[5];
    const float* bhh = (const float*)d_in[6];
    float* out = (float*)d_out;

    lstm_init_kernel<<<(2 * BM + 255) / 256, 256>>>(h, c);
    pack_x_kernel<<<(Bn * Tn * Nn / 4) / 256, 256>>>(x);
    pack_weights_kernel<<<(2 * TILES * NCHUNK * 1024) / 256, 256>>>(Wih, Whh);

    for (int t = 0; t <= Tn; ++t)
        lstm_step_mma<<<2 * TILES, 256>>>(t, bih, bhh, out);

    lstm_final_kernel<<<(2 * BM + 255) / 256, 256>>>(out);
}

// round 11
// speedup vs baseline: 4.4232x; 1.2022x over previous
#include <cuda_runtime.h>
#include <cuda_bf16.h>
#include <math.h>
#include <stdint.h>

// ---------------- problem dims ----------------
#define Bn 32
#define Tn 256
#define Nn 1024
#define Mn 1024
#define G4 4096
#define BM (Bn * Mn)
#define KC 64                 // K elems per chunk
#define NCHUNK 32             // 2048 / 64 (seg0 = input, seg1 = recurrent)
#define TILES 64              // CTAs per layer; 16 hidden units (64 gate rows) each
#define W_CHUNK_BYTES 16384   // 64 rows x 64 bf16 x (hi+lo) = 8KB + 8KB
#define STAGE_BYTES 24576     // W 16KB + A (4KB hi + 4KB lo)
#define NSTAGE 4
#define SMEM_DYN (1024 + NSTAGE * STAGE_BYTES)   // 99328
#define A_HI_OFF 16384
#define A_LO_OFF 20480
#define SWZ(o) ((o) ^ (((o) >> 3) & 0x70))

// ---------------- persistent device state (static; no allocs) ----------------
__device__ float g_h0[2][BM];
__device__ float g_h1[2][BM];
__device__ float g_c0[BM];
__device__ float g_c1[BM];
__device__ __nv_bfloat16 g_h0bf[2][2][BM];          // [dbuf][hi/lo][b*1024+k]
__device__ __nv_bfloat16 g_h1bf[2][2][BM];
__device__ __nv_bfloat16 g_xbf[2][Bn * Tn * Nn];    // [hi/lo], same layout as x
__device__ unsigned char g_Wpk[(size_t)2 * TILES * NCHUNK * W_CHUNK_BYTES];  // 64MB

__device__ __forceinline__ float sigmoidf_(float z) { return 1.0f / (1.0f + expf(-z)); }

__device__ __forceinline__ uint32_t smem_u32(const void* p) {
    uint32_t a;
    asm("{ .reg .u64 t; cvta.to.shared.u64 t, %1; cvt.u32.u64 %0, t; }" : "=r"(a) : "l"(p));
    return a;
}

__device__ __forceinline__ void split2(float a, float b, uint32_t& hi, uint32_t& lo) {
    __nv_bfloat16 ha = __float2bfloat16(a), hb = __float2bfloat16(b);
    float ra = a - __bfloat162float(ha), rb = b - __bfloat162float(hb);
    __nv_bfloat16 la = __float2bfloat16(ra), lb = __float2bfloat16(rb);
    hi = (uint32_t)__bfloat16_as_ushort(ha) | ((uint32_t)__bfloat16_as_ushort(hb) << 16);
    lo = (uint32_t)__bfloat16_as_ushort(la) | ((uint32_t)__bfloat16_as_ushort(lb) << 16);
}

#define LDSM4(R, A)                                                                  \
    asm volatile("ldmatrix.sync.aligned.m8n8.x4.shared.b16 {%0,%1,%2,%3}, [%4];"     \
                 : "=r"((R)[0]), "=r"((R)[1]), "=r"((R)[2]), "=r"((R)[3]) : "r"(A))

#define MMA16816(D, Av, B0, B1)                                                      \
    asm volatile("mma.sync.aligned.m16n8k16.row.col.f32.bf16.bf16.f32 "              \
                 "{%0,%1,%2,%3},{%4,%5,%6,%7},{%8,%9},{%0,%1,%2,%3};"                \
                 : "+f"((D)[0]), "+f"((D)[1]), "+f"((D)[2]), "+f"((D)[3])            \
                 : "r"((Av)[0]), "r"((Av)[1]), "r"((Av)[2]), "r"((Av)[3]),           \
                   "r"(B0), "r"(B1))

#define CPA16(dst, src) \
    asm volatile("cp.async.ca.shared.global [%0], [%1], 16;" :: "r"(dst), "l"(src))
#define CPCOMMIT() asm volatile("cp.async.commit_group;" ::: "memory")

// ---------------- init ----------------
__global__ void lstm_init_kernel(const float* __restrict__ h, const float* __restrict__ c) {
    int i = blockIdx.x * blockDim.x + threadIdx.x;
    if (i < BM) {
        float hv = h[i];
        g_h0[0][i] = hv;  g_c0[i] = c[i];
        __nv_bfloat16 hi = __float2bfloat16(hv);
        g_h0bf[0][0][i] = hi;
        g_h0bf[0][1][i] = __float2bfloat16(hv - __bfloat162float(hi));
    } else if (i < 2 * BM) {
        int j = i - BM;
        float hv = h[i];
        g_h1[0][j] = hv;  g_c1[j] = c[i];
        __nv_bfloat16 hi = __float2bfloat16(hv);
        g_h1bf[0][0][j] = hi;
        g_h1bf[0][1][j] = __float2bfloat16(hv - __bfloat162float(hi));
    }
}

// ---------------- final ----------------
__global__ void lstm_final_kernel(float* __restrict__ out) {
    int i = blockIdx.x * blockDim.x + threadIdx.x;
    if (i >= 2 * BM) return;
    const int base = Bn * Tn * Mn;
    float hv, cv;
    if (i < BM) { hv = g_h0[0][i];      cv = g_c0[i]; }
    else        { hv = g_h1[0][i - BM]; cv = g_c1[i - BM]; }
    out[base + i] = hv;
    out[base + 2 * BM + i] = cv;
}

// ---------------- pack x: fp32 -> bf16 hi/lo ----------------
__global__ void pack_x_kernel(const float* __restrict__ x) {
    int idx = blockIdx.x * blockDim.x + threadIdx.x;   // one thread per 4 elems
    float4 v = *reinterpret_cast<const float4*>(x + (size_t)idx * 4);
    uint32_t h0, l0, h1, l1;
    split2(v.x, v.y, h0, l0);
    split2(v.z, v.w, h1, l1);
    *reinterpret_cast<uint2*>((char*)g_xbf[0] + (size_t)idx * 8) = make_uint2(h0, h1);
    *reinterpret_cast<uint2*>((char*)g_xbf[1] + (size_t)idx * 8) = make_uint2(l0, l1);
}

// ---------------- pack weights: fp32 -> bf16 hi/lo, tile/chunk-major, pre-swizzled ----------------
__global__ void pack_weights_kernel(const float* __restrict__ Wih, const float* __restrict__ Whh) {
    int idx = blockIdx.x * blockDim.x + threadIdx.x;   // 4,194,304
    int k4    = idx & 15;
    int r     = (idx >> 4) & 63;
    int chunk = (idx >> 10) & 31;
    int tile  = (idx >> 15) & 63;
    int l     = (idx >> 21) & 1;
    int gate = r >> 4, ul = r & 15;
    int R = gate * 1024 + tile * 16 + ul;
    int seg = chunk >> 4, k0 = (chunk & 15) * KC;
    const float* W = seg ? Whh : Wih;
    float4 v = *reinterpret_cast<const float4*>(W + ((size_t)l * G4 + R) * 1024 + k0 + k4 * 4);
    uint32_t h0, l0, h1, l1;
    split2(v.x, v.y, h0, l0);
    split2(v.z, v.w, h1, l1);
    size_t base = (size_t)((l * TILES + tile) * NCHUNK + chunk) * W_CHUNK_BYTES;
    uint32_t sw = SWZ((uint32_t)(r * 128 + k4 * 8));
    *reinterpret_cast<uint2*>(g_Wpk + base + sw)        = make_uint2(h0, h1);  // hi (8KB)
    *reinterpret_cast<uint2*>(g_Wpk + base + 8192 + sw) = make_uint2(l0, l1);  // lo (8KB)
}

// ---------------- step kernel: skewed 2-layer, 512 threads, 4-stage cp.async ring ----------------
// grid = 128: blocks 0..63 layer0 step t, 64..127 layer1 step t-1.
// CTA = 16 units (64 gate rows) x 32 batch. 16 warps:
//   rg = wid>>2 (16-row group), nh = (wid>>1)&1 (16-batch half), kid = wid&1 (k-split).
__global__ __launch_bounds__(512, 1)
void lstm_step_mma(int t,
                   const float* __restrict__ bih, const float* __restrict__ bhh,
                   float* __restrict__ out) {
    const int layer = blockIdx.x >> 6;
    const int tile  = blockIdx.x & 63;
    if (layer == 0 && t >= Tn) return;
    if (layer == 1 && t == 0)  return;
    const int s = layer ? (t - 1) : t;
    const int U = tile * 16;
    const int tid = threadIdx.x;
    const int wid = tid >> 5, lane = tid & 31;

    // activation sources (bf16 hi/lo, k-major rows) + state targets
    const char *hi0, *lo0, *hi1, *lo1;
    size_t st0;
    const size_t st1 = (size_t)Mn * 2;
    float* hout; float* cst;
    __nv_bfloat16 *hbo_hi, *hbo_lo;
    if (layer == 0) {
        hi0 = (const char*)g_xbf[0] + (size_t)t * Nn * 2;
        lo0 = (const char*)g_xbf[1] + (size_t)t * Nn * 2;
        st0 = (size_t)Tn * Nn * 2;
        hi1 = (const char*)g_h0bf[t & 1][0];
        lo1 = (const char*)g_h0bf[t & 1][1];
        hout = g_h0[(t & 1) ^ 1]; cst = g_c0;
        hbo_hi = g_h0bf[(t & 1) ^ 1][0]; hbo_lo = g_h0bf[(t & 1) ^ 1][1];
    } else {
        hi0 = (const char*)g_h0bf[t & 1][0];
        lo0 = (const char*)g_h0bf[t & 1][1];
        st0 = st1;
        hi1 = (const char*)g_h1bf[s & 1][0];
        lo1 = (const char*)g_h1bf[s & 1][1];
        hout = g_h1[(s & 1) ^ 1]; cst = g_c1;
        hbo_hi = g_h1bf[(s & 1) ^ 1][0]; hbo_lo = g_h1bf[(s & 1) ^ 1][1];
    }

    extern __shared__ __align__(16) char smraw[];
    const uint32_t sraw = smem_u32(smraw);
    const uint32_t sb   = (sraw + 1023) & ~1023u;       // 1KB-align for swizzle/bank layout
    char* sgen = smraw + (sb - sraw);
    const unsigned char* wsrc = g_Wpk + (size_t)((layer * TILES + tile) * NCHUNK) * W_CHUNK_BYTES;

    // warp roles
    const int rg  = wid >> 2;
    const int nh  = (wid >> 1) & 1;
    const int kid = wid & 1;                  // k-split: ks = kid*2 + j
    const uint32_t woff0 = (uint32_t)((rg * 16 + (lane & 15)) * 128 + (lane >> 4) * 16);
    const uint32_t aoff0 = (uint32_t)((nh * 16 + ((lane >> 4) << 3) + (lane & 7)) * 128
                                      + ((lane >> 3) & 1) * 16);

    float acc[6][4];
#pragma unroll
    for (int i = 0; i < 6; i++)
#pragma unroll
        for (int j = 0; j < 4; j++) acc[i][j] = 0.0f;

    // per-thread fill constants: W 2x16B granules, A 1x16B granule
    const int ap_ = tid >> 8;                 // 0 = hi, 1 = lo
    const int ar_ = (tid >> 3) & 31;          // batch row
    const int akq_ = tid & 7;                 // 16B column within 128B row
    const uint32_t a_dst_off = (ap_ ? A_LO_OFF : A_HI_OFF)
                               + SWZ((uint32_t)(ar_ * 128 + akq_ * 16));

#define FILL(buf_, chk_)                                                             \
    do {                                                                             \
        uint32_t d_ = sb + (buf_) * STAGE_BYTES;                                     \
        const unsigned char* ws_ = wsrc + (size_t)(chk_) * W_CHUNK_BYTES;            \
        CPA16(d_ + tid * 16,        ws_ + tid * 16);                                 \
        CPA16(d_ + 8192 + tid * 16, ws_ + 8192 + tid * 16);                          \
        int seg_ = (chk_) >> 4;                                                      \
        size_t kb_ = (size_t)((chk_) & 15) * KC * 2;                                 \
        const char* asrc_ = (seg_ ? (ap_ ? lo1 : hi1) : (ap_ ? lo0 : hi0))           \
                            + (size_t)ar_ * (seg_ ? st1 : st0) + kb_ + akq_ * 16;    \
        CPA16(d_ + a_dst_off, asrc_);                                                \
    } while (0)

    // ---- prologue: prefetch 3 chunks ----
    FILL(0, 0); CPCOMMIT();
    FILL(1, 1); CPCOMMIT();
    FILL(2, 2); CPCOMMIT();

    // ---- main loop: one barrier per chunk, 3-deep prefetch ----
    for (int c = 0; c < NCHUNK; c++) {
        if (c <= NCHUNK - 3)      asm volatile("cp.async.wait_group 2;" ::: "memory");
        else if (c == NCHUNK - 2) asm volatile("cp.async.wait_group 1;" ::: "memory");
        else                      asm volatile("cp.async.wait_group 0;" ::: "memory");
        __syncthreads();          // everyone's chunk-c copies landed; compute(c-1) done by all

        if (c + 3 < NCHUNK) { FILL((c + 3) & 3, c + 3); CPCOMMIT(); }

        const uint32_t wb = sb + (c & 3) * STAGE_BYTES;
#pragma unroll
        for (int j = 0; j < 2; j++) {
            const int ks = kid * 2 + j;
            uint32_t wo = SWZ(woff0 + ks * 32);
            uint32_t ao = SWZ(aoff0 + ks * 32);
            uint32_t whi[4], wlo[4], ahi[4], alo[4];
            LDSM4(whi, wb + wo);
            LDSM4(wlo, wb + 8192 + wo);
            LDSM4(ahi, wb + A_HI_OFF + ao);
            LDSM4(alo, wb + A_LO_OFF + ao);
            MMA16816(acc[0], whi, ahi[0], ahi[1]);   // ntile0: Whi.Ahi
            MMA16816(acc[3], whi, ahi[2], ahi[3]);   // ntile1: Whi.Ahi
            MMA16816(acc[1], wlo, ahi[0], ahi[1]);   // ntile0: Wlo.Ahi
            MMA16816(acc[4], wlo, ahi[2], ahi[3]);
            MMA16816(acc[2], whi, alo[0], alo[1]);   // ntile0: Whi.Alo
            MMA16816(acc[5], whi, alo[2], alo[3]);
        }
    }
#undef FILL

    // ---- epilogue: frags -> smem z[2][64][33] (k-split planes) -> LSTM update ----
    // z aliases stage buffer 0 (chunk 28's data; all consumers finished).
    float* z = (float*)sgen;
    {
        float* zp = z + kid * (64 * 33);
        const int r0 = rg * 16 + (lane >> 2);
        const int c0 = nh * 16 + (lane & 3) * 2;
#pragma unroll
        for (int nt = 0; nt < 2; nt++) {
            float d0 = acc[nt * 3][0] + acc[nt * 3 + 1][0] + acc[nt * 3 + 2][0];
            float d1 = acc[nt * 3][1] + acc[nt * 3 + 1][1] + acc[nt * 3 + 2][1];
            float d2 = acc[nt * 3][2] + acc[nt * 3 + 1][2] + acc[nt * 3 + 2][2];
            float d3 = acc[nt * 3][3] + acc[nt * 3 + 1][3] + acc[nt * 3 + 2][3];
            int cc = c0 + nt * 8;
            zp[r0 * 33 + cc]           = d0;
            zp[r0 * 33 + cc + 1]       = d1;
            zp[(r0 + 8) * 33 + cc]     = d2;
            zp[(r0 + 8) * 33 + cc + 1] = d3;
        }
    }
    __syncthreads();

    // pointwise: 512 threads -> one (unit, batch) each
    const int ul = tid & 15;
    const int b  = tid >> 4;                  // 0..31
    float bz[4];
#pragma unroll
    for (int g = 0; g < 4; g++) {
        int j = layer * G4 + g * 1024 + U + ul;
        bz[g] = bih[j] + bhh[j];
    }
    float zg4[4];
#pragma unroll
    for (int g = 0; g < 4; g++) {
        int row = g * 16 + ul;
        zg4[g] = z[row * 33 + b] + z[64 * 33 + row * 33 + b] + bz[g];
    }
    {
        int idx = b * Mn + U + ul;
        float ig = sigmoidf_(zg4[0]), fg = sigmoidf_(zg4[1]), og = sigmoidf_(zg4[3]);
        float gg = tanhf(zg4[2]);
        float cn = fmaf(fg, cst[idx], ig * gg);
        cst[idx] = cn;
        float hh = og * tanhf(cn);
        hout[idx] = hh;
        __nv_bfloat16 hhi = __float2bfloat16(hh);
        hbo_hi[idx] = hhi;
        hbo_lo[idx] = __float2bfloat16(hh - __bfloat162float(hhi));
        if (layer == 1)
            out[((size_t)b * Tn + s) * Mn + U + ul] = hh;
    }
}

// ---------------- launch ----------------
extern "C" void kernel_launch(void* const* d_in, const int* in_sizes, int n_in,
                              void* d_out, int out_size) {
    (void)in_sizes; (void)n_in; (void)out_size;
    const float* x   = (const float*)d_in[0];
    const float* h   = (const float*)d_in[1];
    const float* c   = (const float*)d_in[2];
    const float* Wih = (const float*)d_in[3];
    const float* Whh = (const float*)d_in[4];
    const float* bih = (const float*)d_in[5];
    const float* bhh = (const float*)d_in[6];
    float* out = (float*)d_out;

    static int smem_set = 0;
    if (!smem_set) {
        cudaFuncSetAttribute(lstm_step_mma,
                             cudaFuncAttributeMaxDynamicSharedMemorySize, SMEM_DYN);
        smem_set = 1;
    }

    lstm_init_kernel<<<(2 * BM + 255) / 256, 256>>>(h, c);
    pack_x_kernel<<<(Bn * Tn * Nn / 4) / 256, 256>>>(x);
    pack_weights_kernel<<<(2 * TILES * NCHUNK * 1024) / 256, 256>>>(Wih, Whh);

    for (int t = 0; t <= Tn; ++t)
        lstm_step_mma<<<2 * TILES, 512, SMEM_DYN>>>(t, bih, bhh, out);

    lstm_final_kernel<<<(2 * BM + 255) / 256, 256>>>(out);
}

// round 13
// speedup vs baseline: 5.0977x; 1.1525x over previous
#include <cuda_runtime.h>
#include <cuda_bf16.h>
#include <math.h>
#include <stdint.h>

// ---------------- problem dims ----------------
#define Bn 32
#define Tn 256
#define Nn 1024
#define Mn 1024
#define G4 4096
#define BM (Bn * Mn)
#define KC 64                  // K elems per packed sub-chunk
#define NSUB 32                // 2048 / 64 sub-chunks (seg0 input, seg1 recurrent)
#define NMAC 16                // macro-chunks of 2 sub-chunks; group g does mc = g, g+2, ...
#define TILES 64               // CTAs per layer; 16 hidden units (64 gate rows) each
#define W_SUB_BYTES 16384      // 64 rows x 64 bf16 x (hi+lo)
#define SUB_BYTES 24576        // W 16KB + A hi 4KB + A lo 4KB
#define MAC_BYTES 49152        // 2 sub-stages
#define A_HI_OFF 16384
#define A_LO_OFF 20480
#define SMEM_DYN (1024 + 4 * MAC_BYTES)   // 197632: 2 buffers per group
#define SWZ(o) ((o) ^ (((o) >> 3) & 0x70))

// ---------------- persistent device state (static; no allocs) ----------------
__device__ float g_h0[2][BM];
__device__ float g_h1[2][BM];
__device__ float g_c0[BM];
__device__ float g_c1[BM];
__device__ __nv_bfloat16 g_h0bf[2][2][BM];          // [dbuf][hi/lo][b*1024+k]
__device__ __nv_bfloat16 g_h1bf[2][2][BM];
__device__ __nv_bfloat16 g_xbf[2][Bn * Tn * Nn];    // [hi/lo], same layout as x
__device__ unsigned char g_Wpk[(size_t)2 * TILES * NSUB * W_SUB_BYTES];  // 64MB

__device__ __forceinline__ float sigmoidf_(float z) { return 1.0f / (1.0f + expf(-z)); }

__device__ __forceinline__ uint32_t smem_u32(const void* p) {
    uint32_t a;
    asm("{ .reg .u64 t; cvta.to.shared.u64 t, %1; cvt.u32.u64 %0, t; }" : "=r"(a) : "l"(p));
    return a;
}

__device__ __forceinline__ void split2(float a, float b, uint32_t& hi, uint32_t& lo) {
    __nv_bfloat16 ha = __float2bfloat16(a), hb = __float2bfloat16(b);
    float ra = a - __bfloat162float(ha), rb = b - __bfloat162float(hb);
    __nv_bfloat16 la = __float2bfloat16(ra), lb = __float2bfloat16(rb);
    hi = (uint32_t)__bfloat16_as_ushort(ha) | ((uint32_t)__bfloat16_as_ushort(hb) << 16);
    lo = (uint32_t)__bfloat16_as_ushort(la) | ((uint32_t)__bfloat16_as_ushort(lb) << 16);
}

#define LDSM4(R, A)                                                                  \
    asm volatile("ldmatrix.sync.aligned.m8n8.x4.shared.b16 {%0,%1,%2,%3}, [%4];"     \
                 : "=r"((R)[0]), "=r"((R)[1]), "=r"((R)[2]), "=r"((R)[3]) : "r"(A))

#define MMA16816(D, Av, B0, B1)                                                      \
    asm volatile("mma.sync.aligned.m16n8k16.row.col.f32.bf16.bf16.f32 "              \
                 "{%0,%1,%2,%3},{%4,%5,%6,%7},{%8,%9},{%0,%1,%2,%3};"                \
                 : "+f"((D)[0]), "+f"((D)[1]), "+f"((D)[2]), "+f"((D)[3])            \
                 : "r"((Av)[0]), "r"((Av)[1]), "r"((Av)[2]), "r"((Av)[3]),           \
                   "r"(B0), "r"(B1))

#define CPA16(dst, src) \
    asm volatile("cp.async.cg.shared.global [%0], [%1], 16;" :: "r"(dst), "l"(src))
#define CPCOMMIT() asm volatile("cp.async.commit_group;" ::: "memory")
#define GBAR(id) asm volatile("bar.sync %0, 256;" :: "r"(id) : "memory")

// ---------------- init ----------------
__global__ void lstm_init_kernel(const float* __restrict__ h, const float* __restrict__ c) {
    int i = blockIdx.x * blockDim.x + threadIdx.x;
    if (i < BM) {
        float hv = h[i];
        g_h0[0][i] = hv;  g_c0[i] = c[i];
        __nv_bfloat16 hi = __float2bfloat16(hv);
        g_h0bf[0][0][i] = hi;
        g_h0bf[0][1][i] = __float2bfloat16(hv - __bfloat162float(hi));
    } else if (i < 2 * BM) {
        int j = i - BM;
        float hv = h[i];
        g_h1[0][j] = hv;  g_c1[j] = c[i];
        __nv_bfloat16 hi = __float2bfloat16(hv);
        g_h1bf[0][0][j] = hi;
        g_h1bf[0][1][j] = __float2bfloat16(hv - __bfloat162float(hi));
    }
}

// ---------------- final ----------------
__global__ void lstm_final_kernel(float* __restrict__ out) {
    int i = blockIdx.x * blockDim.x + threadIdx.x;
    if (i >= 2 * BM) return;
    const int base = Bn * Tn * Mn;
    float hv, cv;
    if (i < BM) { hv = g_h0[0][i];      cv = g_c0[i]; }
    else        { hv = g_h1[0][i - BM]; cv = g_c1[i - BM]; }
    out[base + i] = hv;
    out[base + 2 * BM + i] = cv;
}

// ---------------- pack x: fp32 -> bf16 hi/lo ----------------
__global__ void pack_x_kernel(const float* __restrict__ x) {
    int idx = blockIdx.x * blockDim.x + threadIdx.x;   // one thread per 4 elems
    float4 v = *reinterpret_cast<const float4*>(x + (size_t)idx * 4);
    uint32_t h0, l0, h1, l1;
    split2(v.x, v.y, h0, l0);
    split2(v.z, v.w, h1, l1);
    *reinterpret_cast<uint2*>((char*)g_xbf[0] + (size_t)idx * 8) = make_uint2(h0, h1);
    *reinterpret_cast<uint2*>((char*)g_xbf[1] + (size_t)idx * 8) = make_uint2(l0, l1);
}

// ---------------- pack weights: fp32 -> bf16 hi/lo, tile/sub-chunk-major, pre-swizzled ----------------
__global__ void pack_weights_kernel(const float* __restrict__ Wih, const float* __restrict__ Whh) {
    int idx = blockIdx.x * blockDim.x + threadIdx.x;   // 4,194,304
    int k4    = idx & 15;
    int r     = (idx >> 4) & 63;
    int chunk = (idx >> 10) & 31;
    int tile  = (idx >> 15) & 63;
    int l     = (idx >> 21) & 1;
    int gate = r >> 4, ul = r & 15;
    int R = gate * 1024 + tile * 16 + ul;
    int seg = chunk >> 4, k0 = (chunk & 15) * KC;
    const float* W = seg ? Whh : Wih;
    float4 v = *reinterpret_cast<const float4*>(W + ((size_t)l * G4 + R) * 1024 + k0 + k4 * 4);
    uint32_t h0, l0, h1, l1;
    split2(v.x, v.y, h0, l0);
    split2(v.z, v.w, h1, l1);
    size_t base = (size_t)((l * TILES + tile) * NSUB + chunk) * W_SUB_BYTES;
    uint32_t sw = SWZ((uint32_t)(r * 128 + k4 * 8));
    *reinterpret_cast<uint2*>(g_Wpk + base + sw)        = make_uint2(h0, h1);  // hi (8KB)
    *reinterpret_cast<uint2*>(g_Wpk + base + 8192 + sw) = make_uint2(l0, l1);  // lo (8KB)
}

// ---------------- step kernel: skewed 2-layer, dual 8-warp pipelines ----------------
// grid = 128: blocks 0..63 layer0 step t, 64..127 layer1 step t-1.
// CTA = 16 units (64 gate rows) x 32 batch. Two 256-thread groups; group g
// processes macro-chunks mc = g, g+2, ... (each macro = 2 packed 64-k sub-chunks),
// synchronized by its OWN named barrier so the groups' stalls overlap.
__global__ __launch_bounds__(512, 1)
void lstm_step_mma(int t,
                   const float* __restrict__ bih, const float* __restrict__ bhh,
                   float* __restrict__ out) {
    const int layer = blockIdx.x >> 6;
    const int tile  = blockIdx.x & 63;
    if (layer == 0 && t >= Tn) return;
    if (layer == 1 && t == 0)  return;
    const int s = layer ? (t - 1) : t;
    const int U = tile * 16;
    const int tid = threadIdx.x;
    const int lane = tid & 31;
    const int grp  = tid >> 8;                 // pipeline group 0/1
    const int gtid = tid & 255;
    const int gwid = (tid >> 5) & 7;           // warp within group

    // activation sources (bf16 hi/lo, k-major rows) + state targets
    const char *hi0, *lo0, *hi1, *lo1;
    size_t st0;
    const size_t st1 = (size_t)Mn * 2;
    float* hout; float* cst;
    __nv_bfloat16 *hbo_hi, *hbo_lo;
    if (layer == 0) {
        hi0 = (const char*)g_xbf[0] + (size_t)t * Nn * 2;
        lo0 = (const char*)g_xbf[1] + (size_t)t * Nn * 2;
        st0 = (size_t)Tn * Nn * 2;
        hi1 = (const char*)g_h0bf[t & 1][0];
        lo1 = (const char*)g_h0bf[t & 1][1];
        hout = g_h0[(t & 1) ^ 1]; cst = g_c0;
        hbo_hi = g_h0bf[(t & 1) ^ 1][0]; hbo_lo = g_h0bf[(t & 1) ^ 1][1];
    } else {
        hi0 = (const char*)g_h0bf[t & 1][0];
        lo0 = (const char*)g_h0bf[t & 1][1];
        st0 = st1;
        hi1 = (const char*)g_h1bf[s & 1][0];
        lo1 = (const char*)g_h1bf[s & 1][1];
        hout = g_h1[(s & 1) ^ 1]; cst = g_c1;
        hbo_hi = g_h1bf[(s & 1) ^ 1][0]; hbo_lo = g_h1bf[(s & 1) ^ 1][1];
    }

    extern __shared__ __align__(16) char smraw[];
    const uint32_t sraw = smem_u32(smraw);
    const uint32_t sb   = (sraw + 1023) & ~1023u;
    char* sgen = smraw + (sb - sraw);
    const unsigned char* wsrc = g_Wpk + (size_t)((layer * TILES + tile) * NSUB) * W_SUB_BYTES;

    // warp roles within group: 4 row-groups x 2 batch-halves; full ks range per warp
    const int rg = gwid >> 1, nh = gwid & 1;
    const uint32_t woff0 = (uint32_t)((rg * 16 + (lane & 15)) * 128 + (lane >> 4) * 16);
    const uint32_t aoff0 = (uint32_t)((nh * 16 + ((lane >> 4) << 3) + (lane & 7)) * 128
                                      + ((lane >> 3) & 1) * 16);

    float acc[6][4];
#pragma unroll
    for (int i = 0; i < 6; i++)
#pragma unroll
        for (int j = 0; j < 4; j++) acc[i][j] = 0.0f;

    // per-thread fill constants (group-local 256 threads)
    const int ar_  = gtid >> 3;                // batch row 0..31
    const int akq_ = gtid & 7;                 // 16B col within 128B row
    const uint32_t a_sw = SWZ((uint32_t)(ar_ * 128 + akq_ * 16));
    const uint32_t gbuf0 = sb + (uint32_t)(2 * grp) * MAC_BYTES;

    // FILL one macro-chunk (2 sub-chunks) into group buffer half
#define FILL(half_, mc_)                                                             \
    do {                                                                             \
        uint32_t d_ = gbuf0 + (half_) * MAC_BYTES;                                   \
        const unsigned char* ws_ = wsrc + (size_t)(mc_) * (2 * W_SUB_BYTES);         \
        _Pragma("unroll")                                                            \
        for (int sc_ = 0; sc_ < 2; sc_++) {                                          \
            uint32_t ds_ = d_ + sc_ * SUB_BYTES;                                     \
            const unsigned char* wss_ = ws_ + sc_ * W_SUB_BYTES;                     \
            _Pragma("unroll")                                                        \
            for (int i_ = 0; i_ < 4; i_++)                                           \
                CPA16(ds_ + i_ * 4096 + gtid * 16, wss_ + i_ * 4096 + gtid * 16);    \
            int sub_ = (mc_) * 2 + sc_;                                              \
            int seg_ = sub_ >> 4;                                                    \
            size_t kb_ = (size_t)(sub_ & 15) * (KC * 2);                             \
            size_t as_ = seg_ ? st1 : st0;                                           \
            const char* sh_ = (seg_ ? hi1 : hi0) + (size_t)ar_ * as_ + kb_ + akq_ * 16; \
            const char* sl_ = (seg_ ? lo1 : lo0) + (size_t)ar_ * as_ + kb_ + akq_ * 16; \
            CPA16(ds_ + A_HI_OFF + a_sw, sh_);                                       \
            CPA16(ds_ + A_LO_OFF + a_sw, sl_);                                       \
        }                                                                            \
    } while (0)

    // ---- prologue: each group fills both its buffers ----
    FILL(0, grp);     CPCOMMIT();
    FILL(1, grp + 2); CPCOMMIT();

    const int barid = grp + 1;

    // ---- per-group pipeline: 8 macro-chunks, 2 group-barriers each ----
    for (int i = 0; i < 8; i++) {
        if (i < 7) asm volatile("cp.async.wait_group 1;" ::: "memory");
        else       asm volatile("cp.async.wait_group 0;" ::: "memory");
        GBAR(barid);                       // macro-chunk i landed for whole group

        const uint32_t mb = gbuf0 + (uint32_t)(i & 1) * MAC_BYTES;
#pragma unroll
        for (int sc = 0; sc < 2; sc++) {
            const uint32_t wb = mb + sc * SUB_BYTES;
#pragma unroll
            for (int ks = 0; ks < 4; ks++) {
                uint32_t wo = SWZ(woff0 + ks * 32);
                uint32_t ao = SWZ(aoff0 + ks * 32);
                uint32_t whi[4], wlo[4], ahi[4], alo[4];
                LDSM4(whi, wb + wo);
                LDSM4(wlo, wb + 8192 + wo);
                LDSM4(ahi, wb + A_HI_OFF + ao);
                LDSM4(alo, wb + A_LO_OFF + ao);
                MMA16816(acc[0], whi, ahi[0], ahi[1]);   // nt0: Whi.Ahi
                MMA16816(acc[3], whi, ahi[2], ahi[3]);   // nt1: Whi.Ahi
                MMA16816(acc[1], wlo, ahi[0], ahi[1]);   // nt0: Wlo.Ahi
                MMA16816(acc[4], wlo, ahi[2], ahi[3]);
                MMA16816(acc[2], whi, alo[0], alo[1]);   // nt0: Whi.Alo
                MMA16816(acc[5], whi, alo[2], alo[3]);
            }
        }
        GBAR(barid);                       // group done reading buffer (i&1)
        if (i + 2 < 8) {
            FILL(i & 1, grp + 2 * (i + 2));
            CPCOMMIT();
        }
    }
#undef FILL

    // ---- epilogue: per-group z plane in the group's own (now idle) buffer 0 ----
    {
        float* zp = (float*)(sgen + (size_t)(2 * grp) * MAC_BYTES);
        const int r0 = rg * 16 + (lane >> 2);
        const int c0 = nh * 16 + (lane & 3) * 2;
#pragma unroll
        for (int nt = 0; nt < 2; nt++) {
            float d0 = acc[nt * 3][0] + acc[nt * 3 + 1][0] + acc[nt * 3 + 2][0];
            float d1 = acc[nt * 3][1] + acc[nt * 3 + 1][1] + acc[nt * 3 + 2][1];
            float d2 = acc[nt * 3][2] + acc[nt * 3 + 1][2] + acc[nt * 3 + 2][2];
            float d3 = acc[nt * 3][3] + acc[nt * 3 + 1][3] + acc[nt * 3 + 2][3];
            int cc = c0 + nt * 8;
            zp[r0 * 33 + cc]           = d0;
            zp[r0 * 33 + cc + 1]       = d1;
            zp[(r0 + 8) * 33 + cc]     = d2;
            zp[(r0 + 8) * 33 + cc + 1] = d3;
        }
    }
    __syncthreads();   // both groups' planes complete

    // pointwise: 512 threads -> one (unit, batch) each; sum the two group planes
    const float* z0 = (const float*)sgen;
    const float* z1 = (const float*)(sgen + 2 * MAC_BYTES);
    const int ul = tid & 15;
    const int b  = tid >> 4;                  // 0..31
    float zg4[4];
#pragma unroll
    for (int g = 0; g < 4; g++) {
        int j = layer * G4 + g * 1024 + U + ul;
        int row = g * 16 + ul;
        zg4[g] = z0[row * 33 + b] + z1[row * 33 + b] + bih[j] + bhh[j];
    }
    {
        int idx = b * Mn + U + ul;
        float ig = sigmoidf_(zg4[0]), fg = sigmoidf_(zg4[1]), og = sigmoidf_(zg4[3]);
        float gg = tanhf(zg4[2]);
        float cn = fmaf(fg, cst[idx], ig * gg);
        cst[idx] = cn;
        float hh = og * tanhf(cn);
        hout[idx] = hh;
        __nv_bfloat16 hhi = __float2bfloat16(hh);
        hbo_hi[idx] = hhi;
        hbo_lo[idx] = __float2bfloat16(hh - __bfloat162float(hhi));
        if (layer == 1)
            out[((size_t)b * Tn + s) * Mn + U + ul] = hh;
    }
}

// ---------------- launch ----------------
extern "C" void kernel_launch(void* const* d_in, const int* in_sizes, int n_in,
                              void* d_out, int out_size) {
    (void)in_sizes; (void)n_in; (void)out_size;
    const float* x   = (const float*)d_in[0];
    const float* h   = (const float*)d_in[1];
    const float* c   = (const float*)d_in[2];
    const float* Wih = (const float*)d_in[3];
    const float* Whh = (const float*)d_in[4];
    const float* bih = (const float*)d_in[5];
    const float* bhh = (const float*)d_in[6];
    float* out = (float*)d_out;

    static int smem_set = 0;
    if (!smem_set) {
        cudaFuncSetAttribute(lstm_step_mma,
                             cudaFuncAttributeMaxDynamicSharedMemorySize, SMEM_DYN);
        smem_set = 1;
    }

    lstm_init_kernel<<<(2 * BM + 255) / 256, 256>>>(h, c);
    pack_x_kernel<<<(Bn * Tn * Nn / 4) / 256, 256>>>(x);
    pack_weights_kernel<<<(2 * TILES * NSUB * 1024) / 256, 256>>>(Wih, Whh);

    for (int t = 0; t <= Tn; ++t)
        lstm_step_mma<<<2 * TILES, 512, SMEM_DYN>>>(t, bih, bhh, out);

    lstm_final_kernel<<<(2 * BM + 255) / 256, 256>>>(out);
}